// round 8
// baseline (speedup 1.0000x reference)
#include <cuda_runtime.h>

// SSConv2d: per-pixel input-group routed 3x3 conv (64 oc) + maxout group select.
// fp32 FFMA2 path. Block = 32x8 output tile, 384 threads (12 warp-slots), 2
// CTAs/SM (24 warps). Each warp-slot owns a group g (proportional allocation);
// lane l owns out-channels {2l, 2l+1}, so one warp covers all 64 oc of a pixel:
// weight slice per thread = 16 f32x2 pairs (32 regs), x is a true warp
// broadcast, acc commit is one LDS.64/STS.64 row. Input pixels bucketed into
// full-interior (checkless) and edge lists; acc tile in smem with per-tap
// exclusive ownership (barrier between taps => race free, deterministic).

#define TX 32
#define TY 8
#define NPIX (TX * TY)      // 256
#define IN_W 34
#define IN_H 10
#define NIN (IN_W * IN_H)   // 340
#define ACC_STRIDE 68       // 68 floats = 272 B per pixel row
#define NTHREADS 384
#define NSLOTS 12
#define FULL_CAP 184        // interior pixels: max 6*30 = 180
#define EDGE_CAP 164        // edge pixels: max 340-180 = 160

typedef unsigned long long ull;

// pre-packed weights: [tap(9)][g(4)][c2(8)][lane(32)][4 floats]
// float4 at (c2,lane) = { w(2l,c_even), w(2l,c_odd), w(2l+1,c_even), w(2l+1,c_odd) }
__device__ float g_wp[9 * 4 * 8 * 32 * 4];

__global__ void prepack_w(const float* __restrict__ w) {
    int i = blockIdx.x * blockDim.x + threadIdx.x;
    if (i >= 36864) return;
    int j    = i & 3;
    int lane = (i >> 2) & 31;
    int c2   = (i >> 7) & 7;
    int g    = (i >> 10) & 3;
    int tap  = i >> 12;
    int oc = lane * 2 + (j >> 1);
    int c  = c2 * 2 + (j & 1);
    // weight layout: [oc][ic = g*16 + c][ky][kx], tap = ky*3 + kx
    g_wp[i] = w[(oc * 64 + g * 16 + c) * 9 + tap];
}

__device__ __forceinline__ void unpack2(float& lo, float& hi, ull v) {
    asm("mov.b64 {%0, %1}, %2;" : "=f"(lo), "=f"(hi) : "l"(v));
}
__device__ __forceinline__ ull fma2(ull a, ull b, ull c) {
    ull d;
    asm("fma.rn.f32x2 %0, %1, %2, %3;" : "=l"(d) : "l"(a), "l"(b), "l"(c));
    return d;
}
__device__ __forceinline__ ull mul2(ull a, ull b) {
    ull d;
    asm("mul.rn.f32x2 %0, %1, %2;" : "=l"(d) : "l"(a), "l"(b));
    return d;
}

struct PixAcc {
    ull a0, a1;   // a0: oc 2l dot, a1: oc 2l+1 dot (f32x2 partial sums)
    float* ap;
};

// partial dot (16c x 2oc) for one pixel; commit deferred for ILP batching
__device__ __forceinline__ PixAcc pix_compute(
    int xoffB, int accoffB, const char* xb, char* accb,
    const ull (&wE)[8], const ull (&wO)[8])
{
    PixAcc r;
    r.ap = (float*)(accb + accoffB);
    const ulonglong2* xp = (const ulonglong2*)(xb + xoffB);
    ulonglong2 p0 = xp[0];
    ulonglong2 p1 = xp[1];
    r.a0 = mul2(wE[0], p0.x);
    r.a1 = mul2(wO[0], p0.x);
    r.a0 = fma2(wE[1], p0.y, r.a0);
    r.a1 = fma2(wO[1], p0.y, r.a1);
    r.a0 = fma2(wE[2], p1.x, r.a0);
    r.a1 = fma2(wO[2], p1.x, r.a1);
    r.a0 = fma2(wE[3], p1.y, r.a0);
    r.a1 = fma2(wO[3], p1.y, r.a1);
    ulonglong2 p2 = xp[2];
    ulonglong2 p3 = xp[3];
    r.a0 = fma2(wE[4], p2.x, r.a0);
    r.a1 = fma2(wO[4], p2.x, r.a1);
    r.a0 = fma2(wE[5], p2.y, r.a0);
    r.a1 = fma2(wO[5], p2.y, r.a1);
    r.a0 = fma2(wE[6], p3.x, r.a0);
    r.a1 = fma2(wO[6], p3.x, r.a1);
    r.a0 = fma2(wE[7], p3.y, r.a0);
    r.a1 = fma2(wO[7], p3.y, r.a1);
    return r;
}

__device__ __forceinline__ void pix_commit(const PixAcc& r) {
    float2 av = *(float2*)r.ap;
    float l, h;
    unpack2(l, h, r.a0); av.x += l + h;
    unpack2(l, h, r.a1); av.y += l + h;
    *(float2*)r.ap = av;
}

#define SMEM_BYTES ((NIN * 16 + NPIX * ACC_STRIDE) * 4 + \
                    4 * FULL_CAP * 4 + 4 * EDGE_CAP * 4 + 32)

extern __shared__ float smem_dyn[];

__global__ __launch_bounds__(NTHREADS, 2)
void ssconv_main(const float* __restrict__ x, const int* __restrict__ gidx,
                 const float* __restrict__ bias, float* __restrict__ out,
                 float* __restrict__ out_idx, int write_idx) {
    float* x_s = smem_dyn;
    float* acc_s = x_s + NIN * 16;
    unsigned* fl = (unsigned*)(acc_s + NPIX * ACC_STRIDE);
    unsigned* el = fl + 4 * FULL_CAP;
    int* cntf = (int*)(el + 4 * EDGE_CAP);
    int* cnte = cntf + 4;

    const int t = threadIdx.x;
    const int b = blockIdx.z;
    const int oy0 = blockIdx.y * TY;
    const int ox0 = blockIdx.x * TX;

    if (t < 8) cntf[t] = 0;
    __syncthreads();

    // ---- load input tile (with halo) into smem ----
    for (int f = t; f < NIN * 4; f += NTHREADS) {
        int p = f >> 2, c4 = f & 3;
        int ly = p / IN_W, lx = p - ly * IN_W;
        int iy = oy0 - 1 + ly, ix = ox0 - 1 + lx;
        float4 v = make_float4(0.f, 0.f, 0.f, 0.f);
        if ((unsigned)iy < 256u && (unsigned)ix < 256u)
            v = *(const float4*)(x + (((size_t)b * 256 + iy) * 256 + ix) * 16 + c4 * 4);
        *(float4*)(x_s + p * 16 + c4 * 4) = v;
    }
    // ---- classify input pixels into (g, full/edge) buckets ----
    for (int p = t; p < NIN; p += NTHREADS) {
        int ly = p / IN_W, lx = p - ly * IN_W;
        int iy = oy0 - 1 + ly, ix = ox0 - 1 + lx;
        if ((unsigned)iy < 256u && (unsigned)ix < 256u) {
            int g = gidx[((size_t)b * 256 + iy) * 256 + ix];
            bool full = (ly >= 2) & (ly <= TY - 1) & (lx >= 2) & (lx <= TX - 1);
            if (full) {
                // interior entry: (p << 23) | (acc byte offset); x byte = e>>17
                unsigned e = ((unsigned)p << 23) |
                             (unsigned)((ly * TX + lx) * (ACC_STRIDE * 4));
                fl[g * FULL_CAP + atomicAdd(&cntf[g], 1)] = e;
            } else {
                unsigned e = ((unsigned)p << 10) | (unsigned)((ly << 6) | lx);
                el[g * EDGE_CAP + atomicAdd(&cnte[g], 1)] = e;
            }
        }
    }
    // ---- init accumulators to bias ----
    for (int f = t; f < NPIX * 17; f += NTHREADS) {
        int c4 = f % 17;
        float4 v = make_float4(0.f, 0.f, 0.f, 0.f);
        if (c4 < 16) v = *(const float4*)(bias + c4 * 4);
        ((float4*)acc_s)[f] = v;
    }
    __syncthreads();

    // ---- proportional slot allocation: 12 warp-slots over 4 groups ----
    const int nf0 = cntf[0], nf1 = cntf[1], nf2 = cntf[2], nf3 = cntf[3];
    const int ne0 = cnte[0], ne1 = cnte[1], ne2 = cnte[2], ne3 = cnte[3];
    const int w0 = 2 * nf0 + ne0, w1 = 2 * nf1 + ne1;
    const int w2 = 2 * nf2 + ne2, w3 = 2 * nf3 + ne3;
    const int W = w0 + w1 + w2 + w3;   // >= 360, never 0
    int e0 = 8 * w0 / W, e1 = 8 * w1 / W, e2 = 8 * w2 / W, e3 = 8 * w3 / W;
    int rem = 8 - (e0 + e1 + e2 + e3);
    int f0 = 8 * w0 - e0 * W, f1 = 8 * w1 - e1 * W;
    int f2 = 8 * w2 - e2 * W, f3 = 8 * w3 - e3 * W;
    int r0 = (f1 > f0) + (f2 > f0) + (f3 > f0);
    int r1 = (f0 >= f1) + (f2 > f1) + (f3 > f1);
    int r2 = (f0 >= f2) + (f1 >= f2) + (f3 > f2);
    int r3 = (f0 >= f3) + (f1 >= f3) + (f2 >= f3);
    int s0 = 1 + e0 + (r0 < rem), s1 = 1 + e1 + (r1 < rem);
    int s2 = 1 + e2 + (r2 < rem), s3 = 1 + e3 + (r3 < rem);
    const int S1 = s0, S2 = s0 + s1, S3 = s0 + s1 + s2;

    const int k = t >> 5;  // warp-slot id 0..11
    const int g = (k >= S1) + (k >= S2) + (k >= S3);
    const int rank = k - (g == 0 ? 0 : g == 1 ? S1 : g == 2 ? S2 : S3);
    const int sg = (g == 0 ? s0 : g == 1 ? s1 : g == 2 ? s2 : s3);
    const int nf = (g == 0 ? nf0 : g == 1 ? nf1 : g == 2 ? nf2 : nf3);
    const int ne = (g == 0 ? ne0 : g == 1 ? ne1 : g == 2 ? ne2 : ne3);
    const unsigned* Lf = fl + g * FULL_CAP;
    const unsigned* Le = el + g * EDGE_CAP;

    const int lane = t & 31;
    const char* xb = (const char*)x_s;
    char* accb = (char*)acc_s + lane * 8;   // lane owns oc {2l, 2l+1}

#pragma unroll 1
    for (int tap = 0; tap < 9; tap++) {
        const int ky = tap / 3;
        const int kx = tap - ky * 3;
        const int tapoffB = (ky * TX + kx) * (ACC_STRIDE * 4);

        // this warp's (tap, g) weight slice: 8 LDG.128 (L1-resident hot set)
        ull wE[8], wO[8];
        const ulonglong2* wq =
            (const ulonglong2*)(g_wp + (tap * 4 + g) * 1024) + lane;
#pragma unroll
        for (int c2 = 0; c2 < 8; c2++) {
            ulonglong2 q = wq[c2 * 32];
            wE[c2] = q.x;
            wO[c2] = q.y;
        }

        // full-interior list: checkless, 2 pixels per iteration
        {
            int i = rank * 2;
            const int step = sg * 2;
            for (; i + 1 < nf; i += step) {
                unsigned u0 = Lf[i], u1 = Lf[i + 1];
                PixAcc A = pix_compute((int)(u0 >> 17),
                                       (int)(u0 & 0x1FFFF) - tapoffB,
                                       xb, accb, wE, wO);
                PixAcc B = pix_compute((int)(u1 >> 17),
                                       (int)(u1 & 0x1FFFF) - tapoffB,
                                       xb, accb, wE, wO);
                pix_commit(A);
                pix_commit(B);
            }
            if (i < nf) {
                unsigned u0 = Lf[i];
                PixAcc A = pix_compute((int)(u0 >> 17),
                                       (int)(u0 & 0x1FFFF) - tapoffB,
                                       xb, accb, wE, wO);
                pix_commit(A);
            }
        }
        // edge list: bounds-checked per tap
        for (int i = rank; i < ne; i += sg) {
            unsigned e = Le[i];
            int ly = (e >> 6) & 15, lx = e & 63;
            int oy = ly - ky, ox = lx - kx;
            if ((unsigned)oy < (unsigned)TY && (unsigned)ox < (unsigned)TX) {
                PixAcc A = pix_compute((int)((e >> 10) << 6),
                                       (oy * TX + ox) * (ACC_STRIDE * 4),
                                       xb, accb, wE, wO);
                pix_commit(A);
            }
        }
        __syncthreads();  // acc ownership handoff between taps
    }

    // ---- epilogue: maxout group selection, one thread per pixel ----
    if (t < NPIX) {
        const float* ar = acc_s + t * ACC_STRIDE;
        float best = -3.4e38f;
        int bi = 0;
#pragma unroll
        for (int og = 0; og < 4; og++) {
            float m = -3.4e38f;
#pragma unroll
            for (int kk = 0; kk < 16; kk += 4) {
                float4 v = *(const float4*)(ar + og * 16 + kk);
                m = fmaxf(m, fmaxf(fmaxf(v.x, v.y), fmaxf(v.z, v.w)));
            }
            if (m > best) { best = m; bi = og; }  // first-max tie-break
        }
        int pyl = t >> 5, pxl = t & 31;
        size_t opix = ((size_t)b * 256 + (oy0 + pyl)) * 256 + (ox0 + pxl);
        float4* op = (float4*)(out + opix * 16);
        const float4* sp = (const float4*)(ar + bi * 16);
        op[0] = sp[0];
        op[1] = sp[1];
        op[2] = sp[2];
        op[3] = sp[3];
        if (write_idx) out_idx[opix] = (float)bi;
    }
}

extern "C" void kernel_launch(void* const* d_in, const int* in_sizes, int n_in,
                              void* d_out, int out_size) {
    const float* x = (const float*)d_in[0];
    const int* gi = (const int*)d_in[1];
    const float* w = (const float*)d_in[2];
    const float* bias = (const float*)d_in[3];
    float* out = (float*)d_out;

    const int n_sel = in_sizes[0];  // B*H*W*16 (sel output size)
    const int n_pix = in_sizes[1];  // B*H*W
    const int B = n_pix / (256 * 256);
    const int write_idx = (out_size >= n_sel + n_pix) ? 1 : 0;

    prepack_w<<<(36864 + 255) / 256, 256>>>(w);

    cudaFuncSetAttribute(ssconv_main, cudaFuncAttributeMaxDynamicSharedMemorySize,
                         SMEM_BYTES);
    dim3 grid(256 / TX, 256 / TY, B);
    ssconv_main<<<grid, NTHREADS, SMEM_BYTES>>>(x, gi, bias, out, out + n_sel,
                                                write_idx);
}

// round 9
// speedup vs baseline: 1.1222x; 1.1222x over previous
#include <cuda_runtime.h>

// SSConv2d: per-pixel input-group routed 3x3 conv (64 oc) + maxout group select.
// fp32 FFMA2 path. Block = 32x8 output tile, 256 threads, 2 CTAs/SM.
// 16 half-warp slots over pixels; 8 WARP UNITS allocated to groups
// proportionally to work (largest remainder, >=1 per g) so both half-slots of
// a warp share the same g and identical trip counts (no intra-warp loop
// divergence). Each half-slot holds its (tap,g) weight slice (16c x 4oc) in
// registers via 16 LDG.128 from an L1-resident prepacked layout; x streams
// from smem via broadcast LDS.128; acc in padded smem tile with per-tap
// exclusive ownership (barrier between taps => race free, deterministic).

#define TX 32
#define TY 8
#define NPIX (TX * TY)      // 256
#define IN_W 34
#define IN_H 10
#define NIN (IN_W * IN_H)   // 340
#define ACC_STRIDE 68       // 68 floats = 272 B per pixel row
#define NTHREADS 256
#define FULL_CAP 184        // interior pixels: max 6*30 = 180
#define EDGE_CAP 164        // edge pixels: max 340-180 = 160

typedef unsigned long long ull;

// pre-packed weights: [tap(9)][g(4)][c2(8)][q(2)][ocg(16)][4 floats]
__device__ float g_wp[9 * 4 * 8 * 2 * 16 * 4];

__global__ void prepack_w(const float* __restrict__ w) {
    int i = blockIdx.x * blockDim.x + threadIdx.x;
    if (i >= 36864) return;
    int j   = i & 3;
    int ocg = (i >> 2) & 15;
    int q   = (i >> 6) & 1;
    int c2  = (i >> 7) & 7;
    int g   = (i >> 10) & 3;
    int tap = i >> 12;
    int oc = ocg * 4 + q * 2 + (j >> 1);
    int c  = c2 * 2 + (j & 1);
    g_wp[i] = w[(oc * 64 + g * 16 + c) * 9 + tap];
}

__device__ __forceinline__ void unpack2(float& lo, float& hi, ull v) {
    asm("mov.b64 {%0, %1}, %2;" : "=f"(lo), "=f"(hi) : "l"(v));
}
__device__ __forceinline__ ull fma2(ull a, ull b, ull c) {
    ull d;
    asm("fma.rn.f32x2 %0, %1, %2, %3;" : "=l"(d) : "l"(a), "l"(b), "l"(c));
    return d;
}
__device__ __forceinline__ ull mul2(ull a, ull b) {
    ull d;
    asm("mul.rn.f32x2 %0, %1, %2;" : "=l"(d) : "l"(a), "l"(b));
    return d;
}

struct PixAcc {
    ull a0, a1, a2, a3;
    float* ap;
};

// partial dot (16c x 4oc) for one pixel, byte-offset addressed
__device__ __forceinline__ PixAcc pix_compute(
    int xoffB, int accoffB, const char* xb, char* accb,
    const ull (&wA)[8], const ull (&wB)[8], const ull (&wC)[8], const ull (&wD)[8])
{
    PixAcc r;
    r.ap = (float*)(accb + accoffB);
    const ulonglong2* xp = (const ulonglong2*)(xb + xoffB);
    ulonglong2 p0 = xp[0];
    ulonglong2 p1 = xp[1];
    r.a0 = mul2(wA[0], p0.x);
    r.a1 = mul2(wB[0], p0.x);
    r.a2 = mul2(wC[0], p0.x);
    r.a3 = mul2(wD[0], p0.x);
    r.a0 = fma2(wA[1], p0.y, r.a0);
    r.a1 = fma2(wB[1], p0.y, r.a1);
    r.a2 = fma2(wC[1], p0.y, r.a2);
    r.a3 = fma2(wD[1], p0.y, r.a3);
    r.a0 = fma2(wA[2], p1.x, r.a0);
    r.a1 = fma2(wB[2], p1.x, r.a1);
    r.a2 = fma2(wC[2], p1.x, r.a2);
    r.a3 = fma2(wD[2], p1.x, r.a3);
    r.a0 = fma2(wA[3], p1.y, r.a0);
    r.a1 = fma2(wB[3], p1.y, r.a1);
    r.a2 = fma2(wC[3], p1.y, r.a2);
    r.a3 = fma2(wD[3], p1.y, r.a3);
    ulonglong2 p2 = xp[2];
    ulonglong2 p3 = xp[3];
    r.a0 = fma2(wA[4], p2.x, r.a0);
    r.a1 = fma2(wB[4], p2.x, r.a1);
    r.a2 = fma2(wC[4], p2.x, r.a2);
    r.a3 = fma2(wD[4], p2.x, r.a3);
    r.a0 = fma2(wA[5], p2.y, r.a0);
    r.a1 = fma2(wB[5], p2.y, r.a1);
    r.a2 = fma2(wC[5], p2.y, r.a2);
    r.a3 = fma2(wD[5], p2.y, r.a3);
    r.a0 = fma2(wA[6], p3.x, r.a0);
    r.a1 = fma2(wB[6], p3.x, r.a1);
    r.a2 = fma2(wC[6], p3.x, r.a2);
    r.a3 = fma2(wD[6], p3.x, r.a3);
    r.a0 = fma2(wA[7], p3.y, r.a0);
    r.a1 = fma2(wB[7], p3.y, r.a1);
    r.a2 = fma2(wC[7], p3.y, r.a2);
    r.a3 = fma2(wD[7], p3.y, r.a3);
    return r;
}

__device__ __forceinline__ void pix_commit(const PixAcc& r) {
    float4 av = *(float4*)r.ap;
    float l, h;
    unpack2(l, h, r.a0); av.x += l + h;
    unpack2(l, h, r.a1); av.y += l + h;
    unpack2(l, h, r.a2); av.z += l + h;
    unpack2(l, h, r.a3); av.w += l + h;
    *(float4*)r.ap = av;
}

#define SMEM_BYTES ((NIN * 16 + NPIX * ACC_STRIDE) * 4 + \
                    4 * FULL_CAP * 4 + 4 * EDGE_CAP * 4 + 32)

extern __shared__ float smem_dyn[];

__global__ __launch_bounds__(NTHREADS, 2)
void ssconv_main(const float* __restrict__ x, const int* __restrict__ gidx,
                 const float* __restrict__ bias, float* __restrict__ out,
                 float* __restrict__ out_idx, int write_idx) {
    float* x_s = smem_dyn;
    float* acc_s = x_s + NIN * 16;
    unsigned* fl = (unsigned*)(acc_s + NPIX * ACC_STRIDE);
    unsigned* el = fl + 4 * FULL_CAP;
    int* cntf = (int*)(el + 4 * EDGE_CAP);
    int* cnte = cntf + 4;

    const int t = threadIdx.x;
    const int b = blockIdx.z;
    const int oy0 = blockIdx.y * TY;
    const int ox0 = blockIdx.x * TX;

    if (t < 8) cntf[t] = 0;
    __syncthreads();

    // ---- load input tile (with halo) into smem ----
    for (int f = t; f < NIN * 4; f += NTHREADS) {
        int p = f >> 2, c4 = f & 3;
        int ly = p / IN_W, lx = p - ly * IN_W;
        int iy = oy0 - 1 + ly, ix = ox0 - 1 + lx;
        float4 v = make_float4(0.f, 0.f, 0.f, 0.f);
        if ((unsigned)iy < 256u && (unsigned)ix < 256u)
            v = *(const float4*)(x + (((size_t)b * 256 + iy) * 256 + ix) * 16 + c4 * 4);
        *(float4*)(x_s + p * 16 + c4 * 4) = v;
    }
    // ---- classify input pixels into (g, full/edge) buckets ----
    for (int p = t; p < NIN; p += NTHREADS) {
        int ly = p / IN_W, lx = p - ly * IN_W;
        int iy = oy0 - 1 + ly, ix = ox0 - 1 + lx;
        if ((unsigned)iy < 256u && (unsigned)ix < 256u) {
            int g = gidx[((size_t)b * 256 + iy) * 256 + ix];
            bool full = (ly >= 2) & (ly <= TY - 1) & (lx >= 2) & (lx <= TX - 1);
            if (full) {
                // interior entry: (p << 23) | (acc byte offset); x byte = e>>17
                unsigned e = ((unsigned)p << 23) |
                             (unsigned)((ly * TX + lx) * (ACC_STRIDE * 4));
                fl[g * FULL_CAP + atomicAdd(&cntf[g], 1)] = e;
            } else {
                unsigned e = ((unsigned)p << 10) | (unsigned)((ly << 6) | lx);
                el[g * EDGE_CAP + atomicAdd(&cnte[g], 1)] = e;
            }
        }
    }
    // ---- init accumulators to bias ----
    for (int f = t; f < NPIX * 17; f += NTHREADS) {
        int c4 = f % 17;
        float4 v = make_float4(0.f, 0.f, 0.f, 0.f);
        if (c4 < 16) v = *(const float4*)(bias + c4 * 4);
        ((float4*)acc_s)[f] = v;
    }
    __syncthreads();

    // ---- proportional WARP-unit allocation: 8 warps over 4 groups ----
    // (both half-slots of a warp land in the same g => no intra-warp
    //  loop-trip divergence; largest-remainder rounding, >=1 warp per g)
    const int nf0 = cntf[0], nf1 = cntf[1], nf2 = cntf[2], nf3 = cntf[3];
    const int ne0 = cnte[0], ne1 = cnte[1], ne2 = cnte[2], ne3 = cnte[3];
    const int w0 = 2 * nf0 + ne0, w1 = 2 * nf1 + ne1;
    const int w2 = 2 * nf2 + ne2, w3 = 2 * nf3 + ne3;
    const int W = w0 + w1 + w2 + w3;   // >= 360, never 0
    int e0 = 4 * w0 / W, e1 = 4 * w1 / W, e2 = 4 * w2 / W, e3 = 4 * w3 / W;
    int rem = 4 - (e0 + e1 + e2 + e3);
    int f0 = 4 * w0 - e0 * W, f1 = 4 * w1 - e1 * W;
    int f2 = 4 * w2 - e2 * W, f3 = 4 * w3 - e3 * W;
    int r0 = (f1 > f0) + (f2 > f0) + (f3 > f0);
    int r1 = (f0 >= f1) + (f2 > f1) + (f3 > f1);
    int r2 = (f0 >= f2) + (f1 >= f2) + (f3 > f2);
    int r3 = (f0 >= f3) + (f1 >= f3) + (f2 >= f3);
    int m0 = 1 + e0 + (r0 < rem), m1 = 1 + e1 + (r1 < rem);
    int m2 = 1 + e2 + (r2 < rem), m3 = 1 + e3 + (r3 < rem);
    const int M1 = m0, M2 = m0 + m1, M3 = m0 + m1 + m2;

    const int u = t >> 5;            // warp unit 0..7
    const int g = (u >= M1) + (u >= M2) + (u >= M3);
    const int ur = u - (g == 0 ? 0 : g == 1 ? M1 : g == 2 ? M2 : M3);
    const int mg = (g == 0 ? m0 : g == 1 ? m1 : g == 2 ? m2 : m3);
    const int h = (t >> 4) & 1;      // half within warp
    const int hs = 2 * ur + h;       // half-slot rank within g (of 2*mg)
    const int nf = (g == 0 ? nf0 : g == 1 ? nf1 : g == 2 ? nf2 : nf3);
    const int ne = (g == 0 ? ne0 : g == 1 ? ne1 : g == 2 ? ne2 : ne3);
    const unsigned* Lf = fl + g * FULL_CAP;
    const unsigned* Le = el + g * EDGE_CAP;

    const int ocg = t & 15;
    const char* xb = (const char*)x_s;
    char* accb = (char*)acc_s + ocg * 16;

#pragma unroll 1
    for (int tap = 0; tap < 9; tap++) {
        const int ky = tap / 3;
        const int kx = tap - ky * 3;
        const int tapoffB = (ky * TX + kx) * (ACC_STRIDE * 4);

        // this slot's (tap, g) weight slice: 16 LDG.128 (L1-resident hot set)
        ull wA[8], wB[8], wC[8], wD[8];
        const ulonglong2* wq =
            (const ulonglong2*)(g_wp + (tap * 4 + g) * 1024) + ocg;
#pragma unroll
        for (int c2 = 0; c2 < 8; c2++) {
            ulonglong2 q0 = wq[c2 * 32];
            ulonglong2 q1 = wq[c2 * 32 + 16];
            wA[c2] = q0.x; wB[c2] = q0.y;
            wC[c2] = q1.x; wD[c2] = q1.y;
        }

        // full-interior list: checkless, 2 pixels per iteration, v2 list read
        {
            int i = hs * 2;                 // 8B-aligned pair index
            const int step = mg * 4;
            for (; i + 1 < nf; i += step) {
                uint2 uu = *(const uint2*)(Lf + i);
                PixAcc A = pix_compute((int)(uu.x >> 17),
                                       (int)(uu.x & 0x1FFFF) - tapoffB,
                                       xb, accb, wA, wB, wC, wD);
                PixAcc B = pix_compute((int)(uu.y >> 17),
                                       (int)(uu.y & 0x1FFFF) - tapoffB,
                                       xb, accb, wA, wB, wC, wD);
                pix_commit(A);
                pix_commit(B);
            }
            if (i < nf) {
                unsigned u0 = Lf[i];
                PixAcc A = pix_compute((int)(u0 >> 17),
                                       (int)(u0 & 0x1FFFF) - tapoffB,
                                       xb, accb, wA, wB, wC, wD);
                pix_commit(A);
            }
        }
        // edge list: bounds-checked per tap
        for (int i = hs; i < ne; i += mg * 2) {
            unsigned e = Le[i];
            int ly = (e >> 6) & 15, lx = e & 63;
            int oy = ly - ky, ox = lx - kx;
            if ((unsigned)oy < (unsigned)TY && (unsigned)ox < (unsigned)TX) {
                PixAcc A = pix_compute((int)((e >> 10) << 6),
                                       (oy * TX + ox) * (ACC_STRIDE * 4),
                                       xb, accb, wA, wB, wC, wD);
                pix_commit(A);
            }
        }
        __syncthreads();  // acc ownership handoff between taps
    }

    // ---- epilogue: maxout group selection, one thread per pixel ----
    {
        const float* ar = acc_s + t * ACC_STRIDE;
        float best = -3.4e38f;
        int bi = 0;
#pragma unroll
        for (int og = 0; og < 4; og++) {
            float m = -3.4e38f;
#pragma unroll
            for (int kk = 0; kk < 16; kk += 4) {
                float4 v = *(const float4*)(ar + og * 16 + kk);
                m = fmaxf(m, fmaxf(fmaxf(v.x, v.y), fmaxf(v.z, v.w)));
            }
            if (m > best) { best = m; bi = og; }  // first-max tie-break
        }
        int pyl = t >> 5, pxl = t & 31;
        size_t opix = ((size_t)b * 256 + (oy0 + pyl)) * 256 + (ox0 + pxl);
        float4* op = (float4*)(out + opix * 16);
        const float4* sp = (const float4*)(ar + bi * 16);
        op[0] = sp[0];
        op[1] = sp[1];
        op[2] = sp[2];
        op[3] = sp[3];
        if (write_idx) out_idx[opix] = (float)bi;
    }
}

extern "C" void kernel_launch(void* const* d_in, const int* in_sizes, int n_in,
                              void* d_out, int out_size) {
    const float* x = (const float*)d_in[0];
    const int* gi = (const int*)d_in[1];
    const float* w = (const float*)d_in[2];
    const float* bias = (const float*)d_in[3];
    float* out = (float*)d_out;

    const int n_sel = in_sizes[0];  // B*H*W*16 (sel output size)
    const int n_pix = in_sizes[1];  // B*H*W
    const int B = n_pix / (256 * 256);
    const int write_idx = (out_size >= n_sel + n_pix) ? 1 : 0;

    prepack_w<<<(36864 + 255) / 256, 256>>>(w);

    cudaFuncSetAttribute(ssconv_main, cudaFuncAttributeMaxDynamicSharedMemorySize,
                         SMEM_BYTES);
    dim3 grid(256 / TX, 256 / TY, B);
    ssconv_main<<<grid, NTHREADS, SMEM_BYTES>>>(x, gi, bias, out, out + n_sel,
                                                write_idx);
}

// round 11
// speedup vs baseline: 1.1758x; 1.0477x over previous
#include <cuda_runtime.h>

// SSConv2d: per-pixel input-group routed 3x3 conv (64 oc) + maxout group select.
// fp32 FFMA2 path. Block = 32x8 output tile, 256 threads, 2 CTAs/SM (16 warps,
// RF-capped). 16 half-warp slots allocated to groups proportionally to work.
// Each slot holds its (tap,g) weight slice (16c x 4oc) in registers; the NEXT
// tap's slice is LDG'd into the same (dead) registers BEFORE the per-tap
// barrier so load latency is absorbed by the barrier wait. Edge entries carry
// a 9-bit tap-validity mask (one bit-test per tap instead of decode+compares).
// x streams from smem via broadcast LDS.128; acc in padded smem tile with
// per-tap exclusive ownership (barrier between taps => race free).

#define TX 32
#define TY 8
#define NPIX (TX * TY)      // 256
#define IN_W 34
#define IN_H 10
#define NIN (IN_W * IN_H)   // 340
#define ACC_STRIDE 68       // 68 floats = 272 B per pixel row
#define NTHREADS 256
#define FULL_CAP 184        // interior pixels: max 6*30 = 180
#define EDGE_CAP 164        // edge pixels: max 340-180 = 160

typedef unsigned long long ull;

// pre-packed weights: [tap(9)][g(4)][c2(8)][q(2)][ocg(16)][4 floats]
__device__ float g_wp[9 * 4 * 8 * 2 * 16 * 4];

__global__ void prepack_w(const float* __restrict__ w) {
    int i = blockIdx.x * blockDim.x + threadIdx.x;
    if (i >= 36864) return;
    int j   = i & 3;
    int ocg = (i >> 2) & 15;
    int q   = (i >> 6) & 1;
    int c2  = (i >> 7) & 7;
    int g   = (i >> 10) & 3;
    int tap = i >> 12;
    int oc = ocg * 4 + q * 2 + (j >> 1);
    int c  = c2 * 2 + (j & 1);
    g_wp[i] = w[(oc * 64 + g * 16 + c) * 9 + tap];
}

__device__ __forceinline__ void unpack2(float& lo, float& hi, ull v) {
    asm("mov.b64 {%0, %1}, %2;" : "=f"(lo), "=f"(hi) : "l"(v));
}
__device__ __forceinline__ ull fma2(ull a, ull b, ull c) {
    ull d;
    asm("fma.rn.f32x2 %0, %1, %2, %3;" : "=l"(d) : "l"(a), "l"(b), "l"(c));
    return d;
}
__device__ __forceinline__ ull mul2(ull a, ull b) {
    ull d;
    asm("mul.rn.f32x2 %0, %1, %2;" : "=l"(d) : "l"(a), "l"(b));
    return d;
}

struct PixAcc {
    ull a0, a1, a2, a3;
    float* ap;
};

// partial dot (16c x 4oc) for one pixel, byte-offset addressed
__device__ __forceinline__ PixAcc pix_compute(
    int xoffB, int accoffB, const char* xb, char* accb,
    const ull (&wA)[8], const ull (&wB)[8], const ull (&wC)[8], const ull (&wD)[8])
{
    PixAcc r;
    r.ap = (float*)(accb + accoffB);
    const ulonglong2* xp = (const ulonglong2*)(xb + xoffB);
    ulonglong2 p0 = xp[0];
    ulonglong2 p1 = xp[1];
    r.a0 = mul2(wA[0], p0.x);
    r.a1 = mul2(wB[0], p0.x);
    r.a2 = mul2(wC[0], p0.x);
    r.a3 = mul2(wD[0], p0.x);
    r.a0 = fma2(wA[1], p0.y, r.a0);
    r.a1 = fma2(wB[1], p0.y, r.a1);
    r.a2 = fma2(wC[1], p0.y, r.a2);
    r.a3 = fma2(wD[1], p0.y, r.a3);
    r.a0 = fma2(wA[2], p1.x, r.a0);
    r.a1 = fma2(wB[2], p1.x, r.a1);
    r.a2 = fma2(wC[2], p1.x, r.a2);
    r.a3 = fma2(wD[2], p1.x, r.a3);
    r.a0 = fma2(wA[3], p1.y, r.a0);
    r.a1 = fma2(wB[3], p1.y, r.a1);
    r.a2 = fma2(wC[3], p1.y, r.a2);
    r.a3 = fma2(wD[3], p1.y, r.a3);
    ulonglong2 p2 = xp[2];
    ulonglong2 p3 = xp[3];
    r.a0 = fma2(wA[4], p2.x, r.a0);
    r.a1 = fma2(wB[4], p2.x, r.a1);
    r.a2 = fma2(wC[4], p2.x, r.a2);
    r.a3 = fma2(wD[4], p2.x, r.a3);
    r.a0 = fma2(wA[5], p2.y, r.a0);
    r.a1 = fma2(wB[5], p2.y, r.a1);
    r.a2 = fma2(wC[5], p2.y, r.a2);
    r.a3 = fma2(wD[5], p2.y, r.a3);
    r.a0 = fma2(wA[6], p3.x, r.a0);
    r.a1 = fma2(wB[6], p3.x, r.a1);
    r.a2 = fma2(wC[6], p3.x, r.a2);
    r.a3 = fma2(wD[6], p3.x, r.a3);
    r.a0 = fma2(wA[7], p3.y, r.a0);
    r.a1 = fma2(wB[7], p3.y, r.a1);
    r.a2 = fma2(wC[7], p3.y, r.a2);
    r.a3 = fma2(wD[7], p3.y, r.a3);
    return r;
}

__device__ __forceinline__ void pix_commit(const PixAcc& r) {
    float4 av = *(float4*)r.ap;
    float l, h;
    unpack2(l, h, r.a0); av.x += l + h;
    unpack2(l, h, r.a1); av.y += l + h;
    unpack2(l, h, r.a2); av.z += l + h;
    unpack2(l, h, r.a3); av.w += l + h;
    *(float4*)r.ap = av;
}

#define SMEM_BYTES ((NIN * 16 + NPIX * ACC_STRIDE) * 4 + \
                    4 * FULL_CAP * 4 + 4 * EDGE_CAP * 4 + 32)

extern __shared__ float smem_dyn[];

__global__ __launch_bounds__(NTHREADS, 2)
void ssconv_main(const float* __restrict__ x, const int* __restrict__ gidx,
                 const float* __restrict__ bias, float* __restrict__ out,
                 float* __restrict__ out_idx, int write_idx) {
    float* x_s = smem_dyn;
    float* acc_s = x_s + NIN * 16;
    unsigned* fl = (unsigned*)(acc_s + NPIX * ACC_STRIDE);
    unsigned* el = fl + 4 * FULL_CAP;
    int* cntf = (int*)(el + 4 * EDGE_CAP);
    int* cnte = cntf + 4;

    const int t = threadIdx.x;
    const int b = blockIdx.z;
    const int oy0 = blockIdx.y * TY;
    const int ox0 = blockIdx.x * TX;

    if (t < 8) cntf[t] = 0;
    __syncthreads();

    // ---- load input tile (with halo) into smem ----
    for (int f = t; f < NIN * 4; f += NTHREADS) {
        int p = f >> 2, c4 = f & 3;
        int ly = p / IN_W, lx = p - ly * IN_W;
        int iy = oy0 - 1 + ly, ix = ox0 - 1 + lx;
        float4 v = make_float4(0.f, 0.f, 0.f, 0.f);
        if ((unsigned)iy < 256u && (unsigned)ix < 256u)
            v = *(const float4*)(x + (((size_t)b * 256 + iy) * 256 + ix) * 16 + c4 * 4);
        *(float4*)(x_s + p * 16 + c4 * 4) = v;
    }
    // ---- classify input pixels into (g, full/edge) buckets ----
    for (int p = t; p < NIN; p += NTHREADS) {
        int ly = p / IN_W, lx = p - ly * IN_W;
        int iy = oy0 - 1 + ly, ix = ox0 - 1 + lx;
        if ((unsigned)iy < 256u && (unsigned)ix < 256u) {
            int g = gidx[((size_t)b * 256 + iy) * 256 + ix];
            bool full = (ly >= 2) & (ly <= TY - 1) & (lx >= 2) & (lx <= TX - 1);
            if (full) {
                // interior entry: (p << 23) | (acc byte offset); x byte = e>>17
                unsigned e = ((unsigned)p << 23) |
                             (unsigned)((ly * TX + lx) * (ACC_STRIDE * 4));
                fl[g * FULL_CAP + atomicAdd(&cntf[g], 1)] = e;
            } else {
                // edge entry: pos(10b)<<18 | p(9b)<<9 | tap-valid mask(9b)
                // mask bit (ky*3+kx) set iff output (ly-ky, lx-kx) is in-tile
                int C = (lx <= TX - 1 ? 1 : 0) |
                        ((lx >= 1 && lx <= TX ? 1 : 0) << 1) |
                        ((lx >= 2 ? 1 : 0) << 2);
                unsigned mask =
                    (ly <= TY - 1 ? C : 0) |
                    ((ly >= 1 && ly <= TY ? C : 0) << 3) |
                    ((ly >= 2 ? C : 0) << 6);
                unsigned e = ((unsigned)(ly * TX + lx) << 18) |
                             ((unsigned)p << 9) | mask;
                el[g * EDGE_CAP + atomicAdd(&cnte[g], 1)] = e;
            }
        }
    }
    // ---- init accumulators to bias ----
    for (int f = t; f < NPIX * 17; f += NTHREADS) {
        int c4 = f % 17;
        float4 v = make_float4(0.f, 0.f, 0.f, 0.f);
        if (c4 < 16) v = *(const float4*)(bias + c4 * 4);
        ((float4*)acc_s)[f] = v;
    }
    __syncthreads();

    // ---- proportional slot allocation: 16 half-warp slots over 4 groups ----
    const int nf0 = cntf[0], nf1 = cntf[1], nf2 = cntf[2], nf3 = cntf[3];
    const int ne0 = cnte[0], ne1 = cnte[1], ne2 = cnte[2], ne3 = cnte[3];
    const int w0 = 2 * nf0 + ne0, w1 = 2 * nf1 + ne1;
    const int w2 = 2 * nf2 + ne2, w3 = 2 * nf3 + ne3;
    const int W = w0 + w1 + w2 + w3;   // >= 360, never 0
    int e0 = 12 * w0 / W, e1 = 12 * w1 / W, e2 = 12 * w2 / W, e3 = 12 * w3 / W;
    int rem = 12 - (e0 + e1 + e2 + e3);
    int f0 = 12 * w0 - e0 * W, f1 = 12 * w1 - e1 * W;
    int f2 = 12 * w2 - e2 * W, f3 = 12 * w3 - e3 * W;
    int r0 = (f1 > f0) + (f2 > f0) + (f3 > f0);
    int r1 = (f0 >= f1) + (f2 > f1) + (f3 > f1);
    int r2 = (f0 >= f2) + (f1 >= f2) + (f3 > f2);
    int r3 = (f0 >= f3) + (f1 >= f3) + (f2 >= f3);
    int s0 = 1 + e0 + (r0 < rem), s1 = 1 + e1 + (r1 < rem);
    int s2 = 1 + e2 + (r2 < rem), s3 = 1 + e3 + (r3 < rem);
    const int S1 = s0, S2 = s0 + s1, S3 = s0 + s1 + s2;

    const int k = t >> 4;  // slot id 0..15
    const int g = (k >= S1) + (k >= S2) + (k >= S3);
    const int rank = k - (g == 0 ? 0 : g == 1 ? S1 : g == 2 ? S2 : S3);
    const int sg = (g == 0 ? s0 : g == 1 ? s1 : g == 2 ? s2 : s3);
    const int nf = (g == 0 ? nf0 : g == 1 ? nf1 : g == 2 ? nf2 : nf3);
    const int ne = (g == 0 ? ne0 : g == 1 ? ne1 : g == 2 ? ne2 : ne3);
    const unsigned* Lf = fl + g * FULL_CAP;
    const unsigned* Le = el + g * EDGE_CAP;

    const int ocg = t & 15;
    const char* xb = (const char*)x_s;
    char* accb = (char*)acc_s + ocg * 16;

    // ---- preload tap 0 weights ----
    ull wA[8], wB[8], wC[8], wD[8];
    {
        const ulonglong2* wq = (const ulonglong2*)(g_wp + g * 1024) + ocg;
#pragma unroll
        for (int c2 = 0; c2 < 8; c2++) {
            ulonglong2 q0 = wq[c2 * 32];
            ulonglong2 q1 = wq[c2 * 32 + 16];
            wA[c2] = q0.x; wB[c2] = q0.y;
            wC[c2] = q1.x; wD[c2] = q1.y;
        }
    }

#pragma unroll 1
    for (int tap = 0; tap < 9; tap++) {
        const int ky = tap / 3;
        const int kx = tap - ky * 3;
        const int tapoffB = (ky * TX + kx) * (ACC_STRIDE * 4);

        // full-interior list: checkless, 2 pixels per iteration
        {
            int i = rank * 2;
            const int step = sg * 2;
            for (; i + 1 < nf; i += step) {
                unsigned u0 = Lf[i], u1 = Lf[i + 1];
                PixAcc A = pix_compute((int)(u0 >> 17),
                                       (int)(u0 & 0x1FFFF) - tapoffB,
                                       xb, accb, wA, wB, wC, wD);
                PixAcc B = pix_compute((int)(u1 >> 17),
                                       (int)(u1 & 0x1FFFF) - tapoffB,
                                       xb, accb, wA, wB, wC, wD);
                pix_commit(A);
                pix_commit(B);
            }
            if (i < nf) {
                unsigned u0 = Lf[i];
                PixAcc A = pix_compute((int)(u0 >> 17),
                                       (int)(u0 & 0x1FFFF) - tapoffB,
                                       xb, accb, wA, wB, wC, wD);
                pix_commit(A);
            }
        }
        // edge list: one bit-test per tap via precomputed validity mask
        for (int i = rank; i < ne; i += sg) {
            unsigned e = Le[i];
            if ((e >> tap) & 1u) {
                int xoffB = (int)((e >> 9) & 511u) << 6;
                int accoffB = (int)(e >> 18) * (ACC_STRIDE * 4) - tapoffB;
                PixAcc A = pix_compute(xoffB, accoffB,
                                       xb, accb, wA, wB, wC, wD);
                pix_commit(A);
            }
        }

        // ---- prefetch NEXT tap's weights into the (now dead) registers,
        //      BEFORE the barrier: LDG latency hides behind the barrier wait.
        //      (pointer arithmetic in FLOAT units, then cast — the R10 bug
        //       was doing "+4096 floats" in ulonglong2 units.)
        if (tap < 8) {
            const ulonglong2* wq =
                (const ulonglong2*)(g_wp + ((tap + 1) * 4 + g) * 1024) + ocg;
#pragma unroll
            for (int c2 = 0; c2 < 8; c2++) {
                ulonglong2 q0 = wq[c2 * 32];
                ulonglong2 q1 = wq[c2 * 32 + 16];
                wA[c2] = q0.x; wB[c2] = q0.y;
                wC[c2] = q1.x; wD[c2] = q1.y;
            }
        }
        __syncthreads();  // acc ownership handoff between taps
    }

    // ---- epilogue: maxout group selection, one thread per pixel ----
    {
        const float* ar = acc_s + t * ACC_STRIDE;
        float best = -3.4e38f;
        int bi = 0;
#pragma unroll
        for (int og = 0; og < 4; og++) {
            float m = -3.4e38f;
#pragma unroll
            for (int kk = 0; kk < 16; kk += 4) {
                float4 v = *(const float4*)(ar + og * 16 + kk);
                m = fmaxf(m, fmaxf(fmaxf(v.x, v.y), fmaxf(v.z, v.w)));
            }
            if (m > best) { best = m; bi = og; }  // first-max tie-break
        }
        int pyl = t >> 5, pxl = t & 31;
        size_t opix = ((size_t)b * 256 + (oy0 + pyl)) * 256 + (ox0 + pxl);
        float4* op = (float4*)(out + opix * 16);
        const float4* sp = (const float4*)(ar + bi * 16);
        op[0] = sp[0];
        op[1] = sp[1];
        op[2] = sp[2];
        op[3] = sp[3];
        if (write_idx) out_idx[opix] = (float)bi;
    }
}

extern "C" void kernel_launch(void* const* d_in, const int* in_sizes, int n_in,
                              void* d_out, int out_size) {
    const float* x = (const float*)d_in[0];
    const int* gi = (const int*)d_in[1];
    const float* w = (const float*)d_in[2];
    const float* bias = (const float*)d_in[3];
    float* out = (float*)d_out;

    const int n_sel = in_sizes[0];  // B*H*W*16 (sel output size)
    const int n_pix = in_sizes[1];  // B*H*W
    const int B = n_pix / (256 * 256);
    const int write_idx = (out_size >= n_sel + n_pix) ? 1 : 0;

    prepack_w<<<(36864 + 255) / 256, 256>>>(w);

    cudaFuncSetAttribute(ssconv_main, cudaFuncAttributeMaxDynamicSharedMemorySize,
                         SMEM_BYTES);
    dim3 grid(256 / TX, 256 / TY, B);
    ssconv_main<<<grid, NTHREADS, SMEM_BYTES>>>(x, gi, bias, out, out + n_sel,
                                                write_idx);
}

// round 12
// speedup vs baseline: 1.2638x; 1.0749x over previous
#include <cuda_runtime.h>

// SSConv2d: per-pixel input-group routed 3x3 conv (64 oc) + maxout group select.
// fp32 FFMA2 path. Block = 32x8 output tile, 256 threads, 2 CTAs/SM (16 warps,
// RF-capped). 16 half-warp slots allocated to groups proportionally to work.
// Each slot holds its (tap,g) weight slice (16c x 4oc) in registers; the NEXT
// tap's slice is LDG'd into the same (dead) registers BEFORE the per-tap
// barrier so load latency hides behind the barrier wait. List entries are
// uint2 with PRECOMPUTED byte offsets (zero-decode hot loop); edge entries
// carry a 9-bit tap-validity mask. Commit folds lo/hi with 4 FADD + 2 packed
// f32x2 adds. x streams from smem via broadcast LDS.128; acc in padded smem
// tile with per-tap exclusive ownership (barrier between taps => race free).

#define TX 32
#define TY 8
#define NPIX (TX * TY)      // 256
#define IN_W 34
#define IN_H 10
#define NIN (IN_W * IN_H)   // 340
#define ACC_STRIDE 68       // 68 floats = 272 B per pixel row
#define NTHREADS 256
#define FULL_CAP 184        // interior pixels: max 6*30 = 180
#define EDGE_CAP 164        // edge pixels: max 340-180 = 160

typedef unsigned long long ull;

// pre-packed weights: [tap(9)][g(4)][c2(8)][q(2)][ocg(16)][4 floats]
__device__ float g_wp[9 * 4 * 8 * 2 * 16 * 4];

__global__ void prepack_w(const float* __restrict__ w) {
    int i = blockIdx.x * blockDim.x + threadIdx.x;
    if (i >= 36864) return;
    int j   = i & 3;
    int ocg = (i >> 2) & 15;
    int q   = (i >> 6) & 1;
    int c2  = (i >> 7) & 7;
    int g   = (i >> 10) & 3;
    int tap = i >> 12;
    int oc = ocg * 4 + q * 2 + (j >> 1);
    int c  = c2 * 2 + (j & 1);
    g_wp[i] = w[(oc * 64 + g * 16 + c) * 9 + tap];
}

__device__ __forceinline__ void unpack2(float& lo, float& hi, ull v) {
    asm("mov.b64 {%0, %1}, %2;" : "=f"(lo), "=f"(hi) : "l"(v));
}
__device__ __forceinline__ ull pack2(float lo, float hi) {
    ull r;
    asm("mov.b64 %0, {%1, %2};" : "=l"(r) : "f"(lo), "f"(hi));
    return r;
}
__device__ __forceinline__ ull fma2(ull a, ull b, ull c) {
    ull d;
    asm("fma.rn.f32x2 %0, %1, %2, %3;" : "=l"(d) : "l"(a), "l"(b), "l"(c));
    return d;
}
__device__ __forceinline__ ull mul2(ull a, ull b) {
    ull d;
    asm("mul.rn.f32x2 %0, %1, %2;" : "=l"(d) : "l"(a), "l"(b));
    return d;
}
__device__ __forceinline__ ull add2(ull a, ull b) {
    ull d;
    asm("add.rn.f32x2 %0, %1, %2;" : "=l"(d) : "l"(a), "l"(b));
    return d;
}

struct PixAcc {
    ull a0, a1, a2, a3;
    float* ap;
};

// partial dot (16c x 4oc) for one pixel, byte-offset addressed
__device__ __forceinline__ PixAcc pix_compute(
    int xoffB, int accoffB, const char* xb, char* accb,
    const ull (&wA)[8], const ull (&wB)[8], const ull (&wC)[8], const ull (&wD)[8])
{
    PixAcc r;
    r.ap = (float*)(accb + accoffB);
    const ulonglong2* xp = (const ulonglong2*)(xb + xoffB);
    ulonglong2 p0 = xp[0];
    ulonglong2 p1 = xp[1];
    r.a0 = mul2(wA[0], p0.x);
    r.a1 = mul2(wB[0], p0.x);
    r.a2 = mul2(wC[0], p0.x);
    r.a3 = mul2(wD[0], p0.x);
    r.a0 = fma2(wA[1], p0.y, r.a0);
    r.a1 = fma2(wB[1], p0.y, r.a1);
    r.a2 = fma2(wC[1], p0.y, r.a2);
    r.a3 = fma2(wD[1], p0.y, r.a3);
    r.a0 = fma2(wA[2], p1.x, r.a0);
    r.a1 = fma2(wB[2], p1.x, r.a1);
    r.a2 = fma2(wC[2], p1.x, r.a2);
    r.a3 = fma2(wD[2], p1.x, r.a3);
    r.a0 = fma2(wA[3], p1.y, r.a0);
    r.a1 = fma2(wB[3], p1.y, r.a1);
    r.a2 = fma2(wC[3], p1.y, r.a2);
    r.a3 = fma2(wD[3], p1.y, r.a3);
    ulonglong2 p2 = xp[2];
    ulonglong2 p3 = xp[3];
    r.a0 = fma2(wA[4], p2.x, r.a0);
    r.a1 = fma2(wB[4], p2.x, r.a1);
    r.a2 = fma2(wC[4], p2.x, r.a2);
    r.a3 = fma2(wD[4], p2.x, r.a3);
    r.a0 = fma2(wA[5], p2.y, r.a0);
    r.a1 = fma2(wB[5], p2.y, r.a1);
    r.a2 = fma2(wC[5], p2.y, r.a2);
    r.a3 = fma2(wD[5], p2.y, r.a3);
    r.a0 = fma2(wA[6], p3.x, r.a0);
    r.a1 = fma2(wB[6], p3.x, r.a1);
    r.a2 = fma2(wC[6], p3.x, r.a2);
    r.a3 = fma2(wD[6], p3.x, r.a3);
    r.a0 = fma2(wA[7], p3.y, r.a0);
    r.a1 = fma2(wB[7], p3.y, r.a1);
    r.a2 = fma2(wC[7], p3.y, r.a2);
    r.a3 = fma2(wD[7], p3.y, r.a3);
    return r;
}

// commit: fold lo/hi per oc (4 FADD), then 2 packed f32x2 adds into the acc
__device__ __forceinline__ void pix_commit(const PixAcc& r) {
    ulonglong2* ap2 = (ulonglong2*)r.ap;
    ulonglong2 av = *ap2;
    float l, h, s0, s1, s2, s3;
    unpack2(l, h, r.a0); s0 = l + h;
    unpack2(l, h, r.a1); s1 = l + h;
    unpack2(l, h, r.a2); s2 = l + h;
    unpack2(l, h, r.a3); s3 = l + h;
    av.x = add2(av.x, pack2(s0, s1));
    av.y = add2(av.y, pack2(s2, s3));
    *ap2 = av;
}

#define SMEM_BYTES ((NIN * 16 + NPIX * ACC_STRIDE) * 4 + \
                    4 * FULL_CAP * 8 + 4 * EDGE_CAP * 8 + 32)

extern __shared__ float smem_dyn[];

__global__ __launch_bounds__(NTHREADS, 2)
void ssconv_main(const float* __restrict__ x, const int* __restrict__ gidx,
                 const float* __restrict__ bias, float* __restrict__ out,
                 float* __restrict__ out_idx, int write_idx) {
    float* x_s = smem_dyn;
    float* acc_s = x_s + NIN * 16;
    uint2* fl = (uint2*)(acc_s + NPIX * ACC_STRIDE);
    uint2* el = fl + 4 * FULL_CAP;
    int* cntf = (int*)(el + 4 * EDGE_CAP);
    int* cnte = cntf + 4;

    const int t = threadIdx.x;
    const int b = blockIdx.z;
    const int oy0 = blockIdx.y * TY;
    const int ox0 = blockIdx.x * TX;

    if (t < 8) cntf[t] = 0;
    __syncthreads();

    // ---- load input tile (with halo) into smem ----
    for (int f = t; f < NIN * 4; f += NTHREADS) {
        int p = f >> 2, c4 = f & 3;
        int ly = p / IN_W, lx = p - ly * IN_W;
        int iy = oy0 - 1 + ly, ix = ox0 - 1 + lx;
        float4 v = make_float4(0.f, 0.f, 0.f, 0.f);
        if ((unsigned)iy < 256u && (unsigned)ix < 256u)
            v = *(const float4*)(x + (((size_t)b * 256 + iy) * 256 + ix) * 16 + c4 * 4);
        *(float4*)(x_s + p * 16 + c4 * 4) = v;
    }
    // ---- classify input pixels into (g, full/edge) buckets ----
    for (int p = t; p < NIN; p += NTHREADS) {
        int ly = p / IN_W, lx = p - ly * IN_W;
        int iy = oy0 - 1 + ly, ix = ox0 - 1 + lx;
        if ((unsigned)iy < 256u && (unsigned)ix < 256u) {
            int g = gidx[((size_t)b * 256 + iy) * 256 + ix];
            unsigned xoffB = (unsigned)p * 64u;
            unsigned posB = (unsigned)(ly * TX + lx) * (ACC_STRIDE * 4);
            bool full = (ly >= 2) & (ly <= TY - 1) & (lx >= 2) & (lx <= TX - 1);
            if (full) {
                fl[g * FULL_CAP + atomicAdd(&cntf[g], 1)] =
                    make_uint2(xoffB, posB);
            } else {
                // edge: y = (posB << 9) | tap-valid mask(9b)
                // mask bit (ky*3+kx) set iff output (ly-ky, lx-kx) in-tile
                unsigned C = (lx <= TX - 1 ? 1u : 0u) |
                             ((lx >= 1 && lx <= TX ? 1u : 0u) << 1) |
                             ((lx >= 2 ? 1u : 0u) << 2);
                unsigned mask =
                    (ly <= TY - 1 ? C : 0u) |
                    ((ly >= 1 && ly <= TY ? C : 0u) << 3) |
                    ((ly >= 2 ? C : 0u) << 6);
                el[g * EDGE_CAP + atomicAdd(&cnte[g], 1)] =
                    make_uint2(xoffB, (posB << 9) | mask);
            }
        }
    }
    // ---- init accumulators to bias ----
    for (int f = t; f < NPIX * 17; f += NTHREADS) {
        int c4 = f % 17;
        float4 v = make_float4(0.f, 0.f, 0.f, 0.f);
        if (c4 < 16) v = *(const float4*)(bias + c4 * 4);
        ((float4*)acc_s)[f] = v;
    }
    __syncthreads();

    // ---- proportional slot allocation: 16 half-warp slots over 4 groups ----
    const int nf0 = cntf[0], nf1 = cntf[1], nf2 = cntf[2], nf3 = cntf[3];
    const int ne0 = cnte[0], ne1 = cnte[1], ne2 = cnte[2], ne3 = cnte[3];
    const int w0 = 2 * nf0 + ne0, w1 = 2 * nf1 + ne1;
    const int w2 = 2 * nf2 + ne2, w3 = 2 * nf3 + ne3;
    const int W = w0 + w1 + w2 + w3;   // >= 360, never 0
    int e0 = 12 * w0 / W, e1 = 12 * w1 / W, e2 = 12 * w2 / W, e3 = 12 * w3 / W;
    int rem = 12 - (e0 + e1 + e2 + e3);
    int f0 = 12 * w0 - e0 * W, f1 = 12 * w1 - e1 * W;
    int f2 = 12 * w2 - e2 * W, f3 = 12 * w3 - e3 * W;
    int r0 = (f1 > f0) + (f2 > f0) + (f3 > f0);
    int r1 = (f0 >= f1) + (f2 > f1) + (f3 > f1);
    int r2 = (f0 >= f2) + (f1 >= f2) + (f3 > f2);
    int r3 = (f0 >= f3) + (f1 >= f3) + (f2 >= f3);
    int s0 = 1 + e0 + (r0 < rem), s1 = 1 + e1 + (r1 < rem);
    int s2 = 1 + e2 + (r2 < rem), s3 = 1 + e3 + (r3 < rem);
    const int S1 = s0, S2 = s0 + s1, S3 = s0 + s1 + s2;

    const int k = t >> 4;  // slot id 0..15
    const int g = (k >= S1) + (k >= S2) + (k >= S3);
    const int rank = k - (g == 0 ? 0 : g == 1 ? S1 : g == 2 ? S2 : S3);
    const int sg = (g == 0 ? s0 : g == 1 ? s1 : g == 2 ? s2 : s3);
    const int nf = (g == 0 ? nf0 : g == 1 ? nf1 : g == 2 ? nf2 : nf3);
    const int ne = (g == 0 ? ne0 : g == 1 ? ne1 : g == 2 ? ne2 : ne3);
    const uint2* Lf = fl + g * FULL_CAP;
    const uint2* Le = el + g * EDGE_CAP;

    const int ocg = t & 15;
    const char* xb = (const char*)x_s;
    char* accb = (char*)acc_s + ocg * 16;

    // ---- preload tap 0 weights ----
    ull wA[8], wB[8], wC[8], wD[8];
    {
        const ulonglong2* wq = (const ulonglong2*)(g_wp + g * 1024) + ocg;
#pragma unroll
        for (int c2 = 0; c2 < 8; c2++) {
            ulonglong2 q0 = wq[c2 * 32];
            ulonglong2 q1 = wq[c2 * 32 + 16];
            wA[c2] = q0.x; wB[c2] = q0.y;
            wC[c2] = q1.x; wD[c2] = q1.y;
        }
    }

#pragma unroll 1
    for (int tap = 0; tap < 9; tap++) {
        const int ky = tap / 3;
        const int kx = tap - ky * 3;
        const int tapoffB = (ky * TX + kx) * (ACC_STRIDE * 4);

        // full-interior list: checkless, 2 pixels via one LDS.128 entry pair
        {
            int i = rank * 2;                // 16B-aligned pair start
            const int step = sg * 2;
            for (; i + 1 < nf; i += step) {
                uint4 uu = *(const uint4*)(Lf + i);
                PixAcc A = pix_compute((int)uu.x, (int)uu.y - tapoffB,
                                       xb, accb, wA, wB, wC, wD);
                PixAcc B = pix_compute((int)uu.z, (int)uu.w - tapoffB,
                                       xb, accb, wA, wB, wC, wD);
                pix_commit(A);
                pix_commit(B);
            }
            if (i < nf) {
                uint2 u0 = Lf[i];
                PixAcc A = pix_compute((int)u0.x, (int)u0.y - tapoffB,
                                       xb, accb, wA, wB, wC, wD);
                pix_commit(A);
            }
        }
        // edge list: one bit-test per tap via precomputed validity mask
        for (int i = rank; i < ne; i += sg) {
            uint2 e = Le[i];
            if ((e.y >> tap) & 1u) {
                int accoffB = (int)(e.y >> 9) - tapoffB;
                PixAcc A = pix_compute((int)e.x, accoffB,
                                       xb, accb, wA, wB, wC, wD);
                pix_commit(A);
            }
        }

        // ---- prefetch NEXT tap's weights (float-unit pointer arithmetic!)
        //      into the now-dead registers BEFORE the barrier
        if (tap < 8) {
            const ulonglong2* wq =
                (const ulonglong2*)(g_wp + ((tap + 1) * 4 + g) * 1024) + ocg;
#pragma unroll
            for (int c2 = 0; c2 < 8; c2++) {
                ulonglong2 q0 = wq[c2 * 32];
                ulonglong2 q1 = wq[c2 * 32 + 16];
                wA[c2] = q0.x; wB[c2] = q0.y;
                wC[c2] = q1.x; wD[c2] = q1.y;
            }
        }
        __syncthreads();  // acc ownership handoff between taps
    }

    // ---- epilogue: maxout group selection, one thread per pixel ----
    {
        const float* ar = acc_s + t * ACC_STRIDE;
        float best = -3.4e38f;
        int bi = 0;
#pragma unroll
        for (int og = 0; og < 4; og++) {
            float m = -3.4e38f;
#pragma unroll
            for (int kk = 0; kk < 16; kk += 4) {
                float4 v = *(const float4*)(ar + og * 16 + kk);
                m = fmaxf(m, fmaxf(fmaxf(v.x, v.y), fmaxf(v.z, v.w)));
            }
            if (m > best) { best = m; bi = og; }  // first-max tie-break
        }
        int pyl = t >> 5, pxl = t & 31;
        size_t opix = ((size_t)b * 256 + (oy0 + pyl)) * 256 + (ox0 + pxl);
        float4* op = (float4*)(out + opix * 16);
        const float4* sp = (const float4*)(ar + bi * 16);
        op[0] = sp[0];
        op[1] = sp[1];
        op[2] = sp[2];
        op[3] = sp[3];
        if (write_idx) out_idx[opix] = (float)bi;
    }
}

extern "C" void kernel_launch(void* const* d_in, const int* in_sizes, int n_in,
                              void* d_out, int out_size) {
    const float* x = (const float*)d_in[0];
    const int* gi = (const int*)d_in[1];
    const float* w = (const float*)d_in[2];
    const float* bias = (const float*)d_in[3];
    float* out = (float*)d_out;

    const int n_sel = in_sizes[0];  // B*H*W*16 (sel output size)
    const int n_pix = in_sizes[1];  // B*H*W
    const int B = n_pix / (256 * 256);
    const int write_idx = (out_size >= n_sel + n_pix) ? 1 : 0;

    prepack_w<<<(36864 + 255) / 256, 256>>>(w);

    cudaFuncSetAttribute(ssconv_main, cudaFuncAttributeMaxDynamicSharedMemorySize,
                         SMEM_BYTES);
    dim3 grid(256 / TX, 256 / TY, B);
    ssconv_main<<<grid, NTHREADS, SMEM_BYTES>>>(x, gi, bias, out, out + n_sel,
                                                write_idx);
}